// round 17
// baseline (speedup 1.0000x reference)
#include <cuda_runtime.h>
#include <stdint.h>

#define THRESH   0.05f
#define SPEC     0.95f      // speculative cutoff; valid because hoi,ps,os < 1
#define NBINS    4096
#define CAP      65536
#define SHN      2048       // max candidates staged in smem (16KB)
#define NLEAF    32

__device__ unsigned int g_leafc[NLEAF];   // monotonic ticket-tree leaves
__device__ unsigned int g_master;         // monotonic ticket-tree root
__device__ unsigned int g_count;          // fast-path candidates (reset by last block)
__device__ unsigned long long g_ck[CAP];  // packed keys, fast path
__device__ unsigned long long g_ck2[CAP]; // packed keys, fallback

// key packs (value, index): key_j > key_i  <=>  j ranks ahead of i
// (value desc, index asc — matches jax.lax.top_k ties). Positive floats:
// uint compare == float compare. Keys unique (indices unique).
__device__ __forceinline__ unsigned long long mk_key(unsigned int vbits, unsigned int idx) {
    return ((unsigned long long)vbits << 32) | (unsigned long long)(0xFFFFFFFFu - idx);
}

__device__ __forceinline__ void push_fast(float v, unsigned int idx) {
    unsigned int pos = atomicAdd(&g_count, 1u);
    if (pos < CAP) g_ck[pos] = mk_key(__float_as_uint(v), idx);
}

// ---------------------------------------------------------------------------
// Scan body (R11 — near DRAM roofline; unchanged).
// ---------------------------------------------------------------------------
__device__ __forceinline__ void scan4(float4 h, unsigned int e, unsigned long long magic,
                                      const float* __restrict__ ps,
                                      const float* __restrict__ os,
                                      unsigned int K) {
    float m = fmaxf(fmaxf(h.x, h.y), fmaxf(h.z, h.w));
    if (m > SPEC) {
        unsigned int r = (unsigned int)(((unsigned long long)e * magic) >> 33);
        unsigned int c = e - r * K;
        float bs0 = ps[r] * os[r];
        float bs1 = bs0;
        if (c + 3 >= K) bs1 = ps[r + 1] * os[r + 1];   // ~2.6% of groups
        float v0 = h.x * bs0;
        float v1 = h.y * ((c + 1 < K) ? bs0 : bs1);
        float v2 = h.z * ((c + 2 < K) ? bs0 : bs1);
        float v3 = h.w * ((c + 3 < K) ? bs0 : bs1);
        if (v0 > SPEC) push_fast(v0, e);
        if (v1 > SPEC) push_fast(v1, e + 1);
        if (v2 > SPEC) push_fast(v2, e + 2);
        if (v3 > SPEC) push_fast(v3, e + 3);
    }
}

// ---------------------------------------------------------------------------
// Write one ranked detection into the flat output:
//   [0,T) scores | [T,5T) pboxes | [5T,9T) oboxes | [9T,10T) ocls
//   [10T,11T) action | [11T,12T) valid
// ---------------------------------------------------------------------------
__device__ __forceinline__ void write_det(unsigned int rank, unsigned long long kb,
                                          const float4* __restrict__ pb,
                                          const float4* __restrict__ ob,
                                          const int* __restrict__ ocls,
                                          float* __restrict__ out,
                                          unsigned int K, int T,
                                          unsigned long long magic) {
    unsigned int vb = (unsigned int)(kb >> 32);
    unsigned int ix = 0xFFFFFFFFu - (unsigned int)(kb & 0xFFFFFFFFu);
    unsigned int pair = (unsigned int)(((unsigned long long)ix * magic) >> 33);
    unsigned int act  = ix - pair * K;
    out[rank] = __uint_as_float(vb);
    float4 p = pb[pair];
    float4 o = ob[pair];
    out[T + 4 * rank + 0] = p.x;  out[T + 4 * rank + 1] = p.y;
    out[T + 4 * rank + 2] = p.z;  out[T + 4 * rank + 3] = p.w;
    out[5 * T + 4 * rank + 0] = o.x;  out[5 * T + 4 * rank + 1] = o.y;
    out[5 * T + 4 * rank + 2] = o.z;  out[5 * T + 4 * rank + 3] = o.w;
    out[9 * T + rank]  = (float)ocls[pair];
    out[10 * T + rank] = (float)act;
    out[11 * T + rank] = 1.0f;
}

// Count keys strictly greater than kb (smem source, x8-unrolled).
__device__ __forceinline__ unsigned int rank_smem(const unsigned long long* sK,
                                                  unsigned int n, unsigned long long kb) {
    unsigned int c = 0, j = 0;
    for (; j + 8u <= n; j += 8u) {
        unsigned int a = 0;
        #pragma unroll
        for (int t = 0; t < 8; t++) a += (sK[j + t] > kb);
        c += a;
    }
    for (; j < n; j++) c += (sK[j] > kb);
    return c;
}

// Count keys strictly greater than kb (global source, x8-unrolled).
__device__ __forceinline__ unsigned int rank_glob(const unsigned long long* __restrict__ keys,
                                                  unsigned int n, unsigned long long kb) {
    unsigned int c = 0, j = 0;
    for (; j + 8u <= n; j += 8u) {
        unsigned int a = 0;
        #pragma unroll
        for (int t = 0; t < 8; t++) a += (__ldcg(keys + j + t) > kb);
        c += a;
    }
    for (; j < n; j++) c += (__ldcg(keys + j) > kb);
    return c;
}

// ---------------------------------------------------------------------------
// ONE kernel, NO grid barrier, NO spinning:
//   scan -> fence -> ticket tree (32 leaves, parallel LTS lines) ->
//   non-last blocks EXIT; the unique last block (all pushes visible) ranks
//   the candidate set from smem and gathers. Exact serial fallback in the
//   last block if the speculative set is unusable (never taken here).
// Requires nblocks % NLEAF == 0 (host guarantees). No co-residency needed.
// ---------------------------------------------------------------------------
__global__ void __launch_bounds__(256)
k_all(const float4* __restrict__ hoi4,
      const float*  __restrict__ ps, const float* __restrict__ os,
      const float4* __restrict__ pb, const float4* __restrict__ ob,
      const int*    __restrict__ ocls, float* __restrict__ out,
      unsigned int nvec, unsigned int N, unsigned int K,
      unsigned long long magic, int T, unsigned int nblocks) {
    __shared__ unsigned long long sK[SHN];   // 16KB; reused as hist in fallback
    __shared__ unsigned int s_last;

    // ---- Phase 1: streaming scan (R11 body, untouched) ----
    {
        unsigned int stride = gridDim.x * blockDim.x;
        unsigned int q = blockIdx.x * blockDim.x + threadIdx.x;
        for (; q + 3u * stride < nvec; q += 4u * stride) {
            float4 h0 = __ldcs(hoi4 + q);
            float4 h1 = __ldcs(hoi4 + q + stride);
            float4 h2 = __ldcs(hoi4 + q + 2u * stride);
            float4 h3 = __ldcs(hoi4 + q + 3u * stride);
            scan4(h0, q * 4u, magic, ps, os, K);
            scan4(h1, (q + stride) * 4u, magic, ps, os, K);
            scan4(h2, (q + 2u * stride) * 4u, magic, ps, os, K);
            scan4(h3, (q + 3u * stride) * 4u, magic, ps, os, K);
        }
        for (; q < nvec; q += stride) {
            float4 h = __ldcs(hoi4 + q);
            scan4(h, q * 4u, magic, ps, os, K);
        }
        if (blockIdx.x == 0 && threadIdx.x == 0) {
            for (unsigned int e = nvec * 4u; e < N; e++) {
                float h = ((const float*)hoi4)[e];
                if (h > SPEC) {
                    unsigned int r = (unsigned int)(((unsigned long long)e * magic) >> 33);
                    float v = h * ps[r] * os[r];
                    if (v > SPEC) push_fast(v, e);
                }
            }
        }
    }

    // ---- Phase 2: ticket tree; non-last blocks exit immediately ----
    __syncthreads();
    __threadfence();   // publish this block's pushes before its ticket
    if (threadIdx.x == 0) {
        s_last = 0;
        unsigned int leafq = nblocks / NLEAF;
        unsigned int leaf = blockIdx.x & (NLEAF - 1u);
        unsigned int t = atomicAdd(&g_leafc[leaf], 1u);
        if ((t % leafq) == leafq - 1u) {                 // leaf full (this round)
            unsigned int m = atomicAdd(&g_master, 1u);
            if ((m % NLEAF) == NLEAF - 1u) s_last = 1;   // ALL blocks arrived
        }
    }
    __syncthreads();
    if (s_last == 0) return;

    // ---- Phase 3: last block only — all candidate pushes are visible ----
    __threadfence();   // acquire side
    unsigned int n = *(volatile unsigned int*)&g_count;
    int tid = threadIdx.x;

    if (n >= (unsigned int)T && n <= SHN) {
        // fast path: stage keys in smem, thread-per-item exact rank
        for (unsigned int i = tid; i < n; i += blockDim.x)
            sK[i] = __ldcg(g_ck + i);
        __syncthreads();
        for (unsigned int i = tid; i < n; i += blockDim.x) {
            unsigned long long kb = sK[i];
            unsigned int rank = rank_smem(sK, n, kb);
            if (rank < (unsigned int)T)
                write_det(rank, kb, pb, ob, ocls, out, K, T, magic);
        }
        __syncthreads();
        if (tid == 0) g_count = 0;
        return;
    }

    // ===== exact serial fallback (single block; never taken for this data) ==
    unsigned int* hist = (unsigned int*)sK;              // 4096 bins = 16KB
    __shared__ unsigned int s_cnt2, s_cut;
    for (int i = tid; i < NBINS; i += blockDim.x) hist[i] = 0;
    if (tid == 0) s_cnt2 = 0;
    __syncthreads();

    const float* hoif = (const float*)hoi4;
    for (unsigned int e = tid; e < N; e += blockDim.x) {
        unsigned int r = (unsigned int)(((unsigned long long)e * magic) >> 33);
        float v = hoif[e] * ps[r] * os[r];
        if (v > THRESH) {
            unsigned int b = (unsigned int)(v * (float)NBINS);
            if (b > NBINS - 1) b = NBINS - 1;
            atomicAdd(&hist[b], 1u);
        }
    }
    __syncthreads();
    if (tid == 0) {
        unsigned int cum = 0, cut = 0;
        for (int b = NBINS - 1; b >= 0; b--) {
            cum += hist[b];
            if (cum >= (unsigned int)T) { cut = (unsigned int)b; break; }
        }
        s_cut = cut;
    }
    __syncthreads();
    unsigned int cut = s_cut;

    for (unsigned int e = tid; e < N; e += blockDim.x) {
        unsigned int r = (unsigned int)(((unsigned long long)e * magic) >> 33);
        float v = hoif[e] * ps[r] * os[r];
        if (v > THRESH) {
            unsigned int b = (unsigned int)(v * (float)NBINS);
            if (b > NBINS - 1) b = NBINS - 1;
            if (b >= cut) {
                unsigned int pos = atomicAdd(&s_cnt2, 1u);
                if (pos < CAP) g_ck2[pos] = mk_key(__float_as_uint(v), e);
            }
        }
    }
    __syncthreads();
    unsigned int n2 = s_cnt2;
    if (n2 > CAP) n2 = CAP;

    for (unsigned int i = tid; i < n2; i += blockDim.x) {
        unsigned long long kb = __ldcg(g_ck2 + i);
        unsigned int rank = rank_glob(g_ck2, n2, kb);
        if (rank < (unsigned int)T)
            write_det(rank, kb, pb, ob, ocls, out, K, T, magic);
    }
    // zero-pad unfilled slots (n2 < T)
    for (int s = tid; s < T; s += blockDim.x) {
        if ((unsigned int)s >= n2) {
            out[s] = 0.0f;
            #pragma unroll
            for (int d = 0; d < 4; d++) {
                out[T + 4 * s + d] = 0.0f;
                out[5 * T + 4 * s + d] = 0.0f;
            }
            out[9 * T + s] = 0.0f;
            out[10 * T + s] = 0.0f;
            out[11 * T + s] = 0.0f;
        }
    }
    __syncthreads();
    if (tid == 0) g_count = 0;
}

// ---------------------------------------------------------------------------
extern "C" void kernel_launch(void* const* d_in, const int* in_sizes, int n_in,
                              void* d_out, int out_size) {
    const float* pb   = (const float*)d_in[0];
    const float* ob   = (const float*)d_in[1];
    const float* ps   = (const float*)d_in[2];
    const float* os   = (const float*)d_in[3];
    const int*   ocls = (const int*)d_in[4];
    const float* hoi  = (const float*)d_in[5];

    int R = in_sizes[2];
    unsigned int N = (unsigned int)in_sizes[5];
    unsigned int K = N / (unsigned int)R;
    int T = out_size / 12;
    unsigned int nvec = N / 4u;
    unsigned long long magic = ((1ULL << 33) + K - 1) / K;  // exact e/K, e < 2^33/K

    int dev = 0, sms = 148;
    cudaGetDevice(&dev);
    cudaDeviceGetAttribute(&sms, cudaDevAttrMultiProcessorCount, dev);

    // multiple of NLEAF; ~8 blocks/SM worth of work (waves OK — no waiting)
    unsigned int blocks = (unsigned int)(((sms * 8) / NLEAF) * NLEAF);

    k_all<<<blocks, 256>>>((const float4*)hoi, ps, os,
                           (const float4*)pb, (const float4*)ob, ocls,
                           (float*)d_out, nvec, N, K, magic, T, blocks);
}